// round 13
// baseline (speedup 1.0000x reference)
#include <cuda_runtime.h>
#include <cuda_bf16.h>
#include <cstdint>

// Problem constants
#define NN   32768
#define FIN  128
#define CC   256
#define HH   4
#define FH   64
#define EE   524288
#define BB   64
#define NPG  512
#define EPG  (EE / BB)
#define K1   256
#define K2   128

// ---------------- scratch (device globals; no allocation allowed) ----------
__device__ float    g_hlin[NN * CC];
__device__ float    g_hout[NN * CC];
__device__ float    g_es[NN * HH];
__device__ float    g_ed[NN * HH];
__device__ int      g_off[NN + 1];
__device__ int      g_csrc[EE];
__device__ float    g_sel[(BB * K1) * CC];
__device__ float    g_pool1[(BB * K1) * CC];
__device__ float    g_pool2[(BB * K2) * CC];

__device__ __forceinline__ float leaky(float x) { return x > 0.f ? x : 0.2f * x; }

// ---------------- tf32 helpers ----------------------------------------------
__device__ __forceinline__ float tf32r(float x) {
    uint32_t u;
    asm("cvt.rna.tf32.f32 %0, %1;" : "=r"(u) : "f"(x));
    return __uint_as_float(u);
}
__device__ __forceinline__ void mma8(float4& d, const uint32_t* a, const uint32_t* b) {
    asm volatile("mma.sync.aligned.m16n8k8.row.col.f32.tf32.tf32.f32 "
        "{%0,%1,%2,%3}, {%4,%5,%6,%7}, {%8,%9}, {%0,%1,%2,%3};"
        : "+f"(d.x), "+f"(d.y), "+f"(d.z), "+f"(d.w)
        : "r"(a[0]), "r"(a[1]), "r"(a[2]), "r"(a[3]), "r"(b[0]), "r"(b[1]));
}

// ---------------- 3xTF32 tensor-core GEMM: C[M,N]=A@B (+bias) ---------------
// 128x128 CTA tile, 256 threads (8 warps, 2x4 grid of 64x32 warp tiles),
// BK=16. A/B split into hi+lo tf32 tiles at the smem stage; 3 mma passes
// (hi*hi, hi*lo, lo*hi) give ~fp32 accuracy. M%128==0, N%128==0, K%16==0.
#define ASTR 20    // [128][20] floats (row stride 20: conflict-free A frags)
#define BSTR 136   // [16][136] floats (row stride 136: conflict-free B frags)
__global__ void __launch_bounds__(256)
tf32_gemm(const float* __restrict__ A, const float* __restrict__ Bm,
          const float* __restrict__ bias, float* __restrict__ Cm,
          int M, int N, int K) {
    __shared__ float As_hi[128 * ASTR];
    __shared__ float As_lo[128 * ASTR];
    __shared__ float Bs_hi[16 * BSTR];
    __shared__ float Bs_lo[16 * BSTR];

    const int tid = threadIdx.x;
    const int lane = tid & 31, wid = tid >> 5;
    const int warp_m = wid & 1, warp_n = wid >> 1;   // 2 x 4 warps
    const int g = lane >> 2, t = lane & 3;
    const int wm0 = warp_m * 64, wn0 = warp_n * 32;
    const int row0 = blockIdx.y * 128;
    const int col0 = blockIdx.x * 128;

    // loader indices (2 float4 each for A and B)
    const int af0 = tid, af1 = tid + 256;            // of 512 float4 (128x4)
    const int arow0 = af0 >> 2, ac0 = (af0 & 3) << 2;
    const int arow1 = af1 >> 2, ac1 = (af1 & 3) << 2;
    const int bf0 = tid, bf1 = tid + 256;            // of 512 float4 (16x32)
    const int brow0 = bf0 >> 5, bc0 = (bf0 & 31) << 2;
    const int brow1 = bf1 >> 5, bc1 = (bf1 & 31) << 2;

    float4 acc[4][4];
#pragma unroll
    for (int i = 0; i < 4; i++)
#pragma unroll
        for (int j = 0; j < 4; j++) acc[i][j] = make_float4(0.f, 0.f, 0.f, 0.f);

    const int ntiles = K >> 4;
    float4 pa0, pa1, pb0, pb1;
    pa0 = *(const float4*)&A[(size_t)(row0 + arow0) * K + ac0];
    pa1 = *(const float4*)&A[(size_t)(row0 + arow1) * K + ac1];
    pb0 = *(const float4*)&Bm[(size_t)brow0 * N + col0 + bc0];
    pb1 = *(const float4*)&Bm[(size_t)brow1 * N + col0 + bc1];

    for (int kt = 0; kt < ntiles; kt++) {
        // split + store staged regs to smem
        {
            const float va0[4] = {pa0.x, pa0.y, pa0.z, pa0.w};
            const float va1[4] = {pa1.x, pa1.y, pa1.z, pa1.w};
            const float vb0[4] = {pb0.x, pb0.y, pb0.z, pb0.w};
            const float vb1[4] = {pb1.x, pb1.y, pb1.z, pb1.w};
            float h[4], l[4];
#pragma unroll
            for (int q = 0; q < 4; q++) { h[q] = tf32r(va0[q]); l[q] = tf32r(va0[q] - h[q]); }
            *(float4*)&As_hi[arow0 * ASTR + ac0] = make_float4(h[0], h[1], h[2], h[3]);
            *(float4*)&As_lo[arow0 * ASTR + ac0] = make_float4(l[0], l[1], l[2], l[3]);
#pragma unroll
            for (int q = 0; q < 4; q++) { h[q] = tf32r(va1[q]); l[q] = tf32r(va1[q] - h[q]); }
            *(float4*)&As_hi[arow1 * ASTR + ac1] = make_float4(h[0], h[1], h[2], h[3]);
            *(float4*)&As_lo[arow1 * ASTR + ac1] = make_float4(l[0], l[1], l[2], l[3]);
#pragma unroll
            for (int q = 0; q < 4; q++) { h[q] = tf32r(vb0[q]); l[q] = tf32r(vb0[q] - h[q]); }
            *(float4*)&Bs_hi[brow0 * BSTR + bc0] = make_float4(h[0], h[1], h[2], h[3]);
            *(float4*)&Bs_lo[brow0 * BSTR + bc0] = make_float4(l[0], l[1], l[2], l[3]);
#pragma unroll
            for (int q = 0; q < 4; q++) { h[q] = tf32r(vb1[q]); l[q] = tf32r(vb1[q] - h[q]); }
            *(float4*)&Bs_hi[brow1 * BSTR + bc1] = make_float4(h[0], h[1], h[2], h[3]);
            *(float4*)&Bs_lo[brow1 * BSTR + bc1] = make_float4(l[0], l[1], l[2], l[3]);
        }
        __syncthreads();
        if (kt + 1 < ntiles) {
            const int k0 = (kt + 1) << 4;
            pa0 = *(const float4*)&A[(size_t)(row0 + arow0) * K + k0 + ac0];
            pa1 = *(const float4*)&A[(size_t)(row0 + arow1) * K + k0 + ac1];
            pb0 = *(const float4*)&Bm[(size_t)(k0 + brow0) * N + col0 + bc0];
            pb1 = *(const float4*)&Bm[(size_t)(k0 + brow1) * N + col0 + bc1];
        }
        const uint32_t* Ah = (const uint32_t*)As_hi;
        const uint32_t* Al = (const uint32_t*)As_lo;
        const uint32_t* Bh = (const uint32_t*)Bs_hi;
        const uint32_t* Bl = (const uint32_t*)Bs_lo;
#pragma unroll
        for (int k8 = 0; k8 < 16; k8 += 8) {
            uint32_t af[4][4], bh[4][2], bl[4][2];
#pragma unroll
            for (int nt = 0; nt < 4; nt++) {
                const int c = wn0 + nt * 8 + g;
                bh[nt][0] = Bh[(k8 + t) * BSTR + c];
                bh[nt][1] = Bh[(k8 + t + 4) * BSTR + c];
                bl[nt][0] = Bl[(k8 + t) * BSTR + c];
                bl[nt][1] = Bl[(k8 + t + 4) * BSTR + c];
            }
#pragma unroll
            for (int mt = 0; mt < 4; mt++) {
                const int r = wm0 + mt * 16 + g;
                af[mt][0] = Ah[r * ASTR + k8 + t];
                af[mt][1] = Ah[(r + 8) * ASTR + k8 + t];
                af[mt][2] = Ah[r * ASTR + k8 + t + 4];
                af[mt][3] = Ah[(r + 8) * ASTR + k8 + t + 4];
            }
#pragma unroll
            for (int mt = 0; mt < 4; mt++)
#pragma unroll
                for (int nt = 0; nt < 4; nt++) {
                    mma8(acc[mt][nt], af[mt], bh[nt]);
                    mma8(acc[mt][nt], af[mt], bl[nt]);
                }
#pragma unroll
            for (int mt = 0; mt < 4; mt++) {
                const int r = wm0 + mt * 16 + g;
                af[mt][0] = Al[r * ASTR + k8 + t];
                af[mt][1] = Al[(r + 8) * ASTR + k8 + t];
                af[mt][2] = Al[r * ASTR + k8 + t + 4];
                af[mt][3] = Al[(r + 8) * ASTR + k8 + t + 4];
            }
#pragma unroll
            for (int mt = 0; mt < 4; mt++)
#pragma unroll
                for (int nt = 0; nt < 4; nt++)
                    mma8(acc[mt][nt], af[mt], bh[nt]);
        }
        __syncthreads();
    }

    // epilogue: bias + store (fragment layout: c0,c1 = cols 2t,2t+1 row g;
    // c2,c3 same cols row g+8)
#pragma unroll
    for (int nt = 0; nt < 4; nt++) {
        const int c = col0 + wn0 + nt * 8 + 2 * t;
        float2 bv = make_float2(0.f, 0.f);
        if (bias) bv = *(const float2*)&bias[c];
#pragma unroll
        for (int mt = 0; mt < 4; mt++) {
            const int r = row0 + wm0 + mt * 16 + g;
            float2 lo2 = make_float2(acc[mt][nt].x + bv.x, acc[mt][nt].y + bv.y);
            float2 hi2 = make_float2(acc[mt][nt].z + bv.x, acc[mt][nt].w + bv.y);
            *(float2*)&Cm[(size_t)r * N + c] = lo2;
            *(float2*)&Cm[(size_t)(r + 8) * N + c] = hi2;
        }
    }
}

// ---------------- single-kernel CSR build (1 CTA per graph) -----------------
__global__ void __launch_bounds__(256)
csr_build(const int* __restrict__ ei) {
    __shared__ int cnt[NPG];
    __shared__ int sh[256];
    const int g = blockIdx.x, tid = threadIdx.x;
    const int ebase = g * EPG, nbase = g * NPG;
    cnt[tid] = 0; cnt[tid + 256] = 0;
    __syncthreads();
#pragma unroll
    for (int i = tid; i < EPG; i += 256)
        atomicAdd(&cnt[ei[EE + ebase + i] - nbase], 1);
    __syncthreads();
    const int c0 = cnt[2 * tid], c1 = cnt[2 * tid + 1];
    const int tot = c0 + c1;
    sh[tid] = tot;
    __syncthreads();
    for (int s = 1; s < 256; s <<= 1) {
        const int v = (tid >= s) ? sh[tid - s] : 0;
        __syncthreads();
        sh[tid] += v;
        __syncthreads();
    }
    const int base = sh[tid] - tot;
    g_off[nbase + 2 * tid]     = ebase + base;
    g_off[nbase + 2 * tid + 1] = ebase + base + c0;
    cnt[2 * tid] = base;
    cnt[2 * tid + 1] = base + c0;
    if (g == BB - 1 && tid == 0) g_off[NN] = EE;
    __syncthreads();
#pragma unroll
    for (int i = tid; i < EPG; i += 256) {
        const int d = ei[EE + ebase + i] - nbase;
        const int p = atomicAdd(&cnt[d], 1);
        g_csrc[ebase + p] = ei[ebase + i];
    }
}

// ---------------- attention logits: es/ed per (node, head) -----------------
__global__ void esed_kernel(const float* __restrict__ hlin,
                            const float* __restrict__ a_src,
                            const float* __restrict__ a_dst,
                            float* __restrict__ es, float* __restrict__ ed) {
    const int w = (blockIdx.x * blockDim.x + threadIdx.x) >> 5;
    const int lane = threadIdx.x & 31;
    if (w >= NN * HH) return;
    const int n = w >> 2, h = w & 3;
    const float* hp = hlin + (size_t)n * CC + h * FH;
    const float v0 = hp[lane], v1 = hp[lane + 32];
    float s = v0 * a_src[h * FH + lane] + v1 * a_src[h * FH + lane + 32];
    float d = v0 * a_dst[h * FH + lane] + v1 * a_dst[h * FH + lane + 32];
#pragma unroll
    for (int o = 16; o; o >>= 1) {
        s += __shfl_xor_sync(0xffffffffu, s, o);
        d += __shfl_xor_sync(0xffffffffu, d, o);
    }
    if (lane == 0) { es[w] = s; ed[w] = d; }
}

// ---------------- fused softmax + aggregate + bias + ELU (R10-proven) -------
__global__ void __launch_bounds__(256)
gat_fused(const int* __restrict__ off, const int* __restrict__ csrc,
          const float* __restrict__ es, const float* __restrict__ ed,
          const float* __restrict__ hlin, const float* __restrict__ bias,
          float* __restrict__ out) {
    const int n = (blockIdx.x * blockDim.x + threadIdx.x) >> 5;
    const int lane = threadIdx.x & 31;
    if (n >= NN) return;

    const float4 edv = ((const float4*)ed)[n];
    const float4 esv = ((const float4*)es)[n];
    const float xs0 = __expf(leaky(esv.x + edv.x));
    const float xs1 = __expf(leaky(esv.y + edv.y));
    const float xs2 = __expf(leaky(esv.z + edv.z));
    const float xs3 = __expf(leaky(esv.w + edv.w));

    const int hi = lane >> 4;
    const float4* hn = (const float4*)(hlin + (size_t)n * CC);
    float4 acc0 = hn[lane];
    float4 acc1 = hn[32 + lane];
    const float sa0 = hi ? xs1 : xs0;
    const float sa1 = hi ? xs3 : xs2;
    acc0.x *= sa0; acc0.y *= sa0; acc0.z *= sa0; acc0.w *= sa0;
    acc1.x *= sa1; acc1.y *= sa1; acc1.z *= sa1; acc1.w *= sa1;

    float ts0 = 0.f, ts1 = 0.f, ts2 = 0.f, ts3 = 0.f;
    const int o0 = off[n], o1 = off[n + 1];
    for (int base = o0; base < o1; base += 32) {
        const int cnt = min(32, o1 - base);
        int s = 0;
        float t0 = 0.f, t1 = 0.f, t2 = 0.f, t3 = 0.f;
        if (lane < cnt) {
            s = csrc[base + lane];
            const float4 ess = ((const float4*)es)[s];
            t0 = __expf(leaky(ess.x + edv.x));
            t1 = __expf(leaky(ess.y + edv.y));
            t2 = __expf(leaky(ess.z + edv.z));
            t3 = __expf(leaky(ess.w + edv.w));
        }
        ts0 += t0; ts1 += t1; ts2 += t2; ts3 += t3;

        int se = __shfl_sync(0xffffffffu, s, 0);
        const float4* hs = (const float4*)(hlin + (size_t)se * CC);
        float4 v0n = hs[lane], v1n = hs[32 + lane];
        for (int e = 0; e < cnt; e++) {
            const float4 v0 = v0n, v1 = v1n;
            const float w0 = __shfl_sync(0xffffffffu, t0, e);
            const float w1 = __shfl_sync(0xffffffffu, t1, e);
            const float w2 = __shfl_sync(0xffffffffu, t2, e);
            const float w3 = __shfl_sync(0xffffffffu, t3, e);
            if (e + 1 < cnt) {
                se = __shfl_sync(0xffffffffu, s, e + 1);
                const float4* hsn = (const float4*)(hlin + (size_t)se * CC);
                v0n = hsn[lane]; v1n = hsn[32 + lane];
            }
            const float aw0 = hi ? w1 : w0;
            const float aw1 = hi ? w3 : w2;
            acc0.x += aw0 * v0.x; acc0.y += aw0 * v0.y;
            acc0.z += aw0 * v0.z; acc0.w += aw0 * v0.w;
            acc1.x += aw1 * v1.x; acc1.y += aw1 * v1.y;
            acc1.z += aw1 * v1.z; acc1.w += aw1 * v1.w;
        }
    }
#pragma unroll
    for (int o = 16; o; o >>= 1) {
        ts0 += __shfl_xor_sync(0xffffffffu, ts0, o);
        ts1 += __shfl_xor_sync(0xffffffffu, ts1, o);
        ts2 += __shfl_xor_sync(0xffffffffu, ts2, o);
        ts3 += __shfl_xor_sync(0xffffffffu, ts3, o);
    }
    const float di0 = 1.f / (xs0 + ts0 + 1e-16f);
    const float di1 = 1.f / (xs1 + ts1 + 1e-16f);
    const float di2 = 1.f / (xs2 + ts2 + 1e-16f);
    const float di3 = 1.f / (xs3 + ts3 + 1e-16f);
    const float d0 = hi ? di1 : di0;
    const float d1 = hi ? di3 : di2;

    const float4 bv0 = ((const float4*)bias)[lane];
    const float4 bv1 = ((const float4*)bias)[32 + lane];
    float4 o0v, o1v;
    o0v.x = acc0.x * d0 + bv0.x; o0v.y = acc0.y * d0 + bv0.y;
    o0v.z = acc0.z * d0 + bv0.z; o0v.w = acc0.w * d0 + bv0.w;
    o1v.x = acc1.x * d1 + bv1.x; o1v.y = acc1.y * d1 + bv1.y;
    o1v.z = acc1.z * d1 + bv1.z; o1v.w = acc1.w * d1 + bv1.w;
    o0v.x = o0v.x > 0.f ? o0v.x : (__expf(o0v.x) - 1.f);
    o0v.y = o0v.y > 0.f ? o0v.y : (__expf(o0v.y) - 1.f);
    o0v.z = o0v.z > 0.f ? o0v.z : (__expf(o0v.z) - 1.f);
    o0v.w = o0v.w > 0.f ? o0v.w : (__expf(o0v.w) - 1.f);
    o1v.x = o1v.x > 0.f ? o1v.x : (__expf(o1v.x) - 1.f);
    o1v.y = o1v.y > 0.f ? o1v.y : (__expf(o1v.y) - 1.f);
    o1v.z = o1v.z > 0.f ? o1v.z : (__expf(o1v.z) - 1.f);
    o1v.w = o1v.w > 0.f ? o1v.w : (__expf(o1v.w) - 1.f);
    ((float4*)out)[(size_t)n * 64 + lane]      = o0v;
    ((float4*)out)[(size_t)n * 64 + 32 + lane] = o1v;
}

// ---------------- fused pooling: score + top-k + gather ---------------------
template <int NPB, int KSEL>
__global__ void pool_fused(const float* __restrict__ X, const float* __restrict__ sw,
                           float* __restrict__ selb) {
    __shared__ float sv[NPB];
    __shared__ int si[NPB];
    const int b = blockIdx.x, t = threadIdx.x;
    const int wid = t >> 5, lane = t & 31;

#pragma unroll
    for (int rr = 0; rr < 32; rr++) {
        const int local = wid * 32 + rr;
        const float* xp = X + (size_t)(b * NPB + local) * CC;
        float s = 0.f;
#pragma unroll
        for (int c = 0; c < CC / 32; c++) s += xp[lane + c * 32] * sw[lane + c * 32];
#pragma unroll
        for (int o = 16; o; o >>= 1) s += __shfl_xor_sync(0xffffffffu, s, o);
        if (lane == 0) { sv[local] = s; si[local] = local; }
    }
    __syncthreads();

    for (int k = 2; k <= NPB; k <<= 1) {
        for (int j = k >> 1; j > 0; j >>= 1) {
            const int ixj = t ^ j;
            if (ixj > t) {
                const bool desc = ((t & k) == 0);
                const float a = sv[t], c = sv[ixj];
                if ((a < c) == desc) {
                    sv[t] = c; sv[ixj] = a;
                    const int tmp = si[t]; si[t] = si[ixj]; si[ixj] = tmp;
                }
            }
            __syncthreads();
        }
    }

    for (int idx = t; idx < KSEL * 64; idx += NPB) {
        const int r = idx >> 6, q = idx & 63;
        const int src = b * NPB + si[r];
        ((float4*)selb)[(size_t)(b * KSEL + r) * 64 + q] =
            ((const float4*)X)[(size_t)src * 64 + q];
    }
}

// ---------------- fused readout: mean + fc1(relu) + fc2 + log_softmax -------
__global__ void __launch_bounds__(256)
readout_fused(const float* __restrict__ X, const float* __restrict__ c1w,
              const float* __restrict__ c1b, const float* __restrict__ c2w,
              const float* __restrict__ c2b, float* __restrict__ out) {
    __shared__ float gm[CC];
    __shared__ float f1[64];
    const int b = blockIdx.x, t = threadIdx.x;
    const int wid = t >> 5, lane = t & 31;

    float s = 0.f;
    const float* xp = X + (size_t)b * K2 * CC + t;
#pragma unroll 4
    for (int r = 0; r < K2; r++) s += xp[r * CC];
    gm[t] = s * (1.f / K2);
    __syncthreads();

#pragma unroll
    for (int oo = 0; oo < 8; oo++) {
        const int o = wid * 8 + oo;
        float acc = 0.f;
#pragma unroll
        for (int c = 0; c < CC / 32; c++)
            acc += gm[lane + c * 32] * c1w[(lane + c * 32) * 64 + o];
#pragma unroll
        for (int off = 16; off; off >>= 1) acc += __shfl_xor_sync(0xffffffffu, acc, off);
        if (lane == 0) {
            const float v = acc + c1b[o];
            f1[o] = v > 0.f ? v : 0.f;
        }
    }
    __syncthreads();

    if (wid == 0) {
        float l0 = 0.f, l1 = 0.f;
#pragma unroll
        for (int k = lane; k < 64; k += 32) {
            const float v = f1[k];
            l0 += v * c2w[k * 2 + 0];
            l1 += v * c2w[k * 2 + 1];
        }
#pragma unroll
        for (int off = 16; off; off >>= 1) {
            l0 += __shfl_xor_sync(0xffffffffu, l0, off);
            l1 += __shfl_xor_sync(0xffffffffu, l1, off);
        }
        if (lane == 0) {
            l0 += c2b[0]; l1 += c2b[1];
            const float mm = fmaxf(l0, l1);
            const float lse = mm + logf(__expf(l0 - mm) + __expf(l1 - mm));
            out[b * 2 + 0] = l0 - lse;
            out[b * 2 + 1] = l1 - lse;
        }
    }
}

// ---------------- host orchestration ----------------------------------------
static float* sym(const void* s) {
    void* p = nullptr;
    cudaGetSymbolAddress(&p, (const void*)s);
    return (float*)p;
}

extern "C" void kernel_launch(void* const* d_in, const int* in_sizes, int n_in,
                              void* d_out, int out_size) {
    const float* x      = (const float*)d_in[0];
    const int*   ei     = (const int*)  d_in[1];
    const float* W1     = (const float*)d_in[3];
    const float* asrc1  = (const float*)d_in[4];
    const float* adst1  = (const float*)d_in[5];
    const float* b1     = (const float*)d_in[6];
    const float* W2     = (const float*)d_in[7];
    const float* asrc2  = (const float*)d_in[8];
    const float* adst2  = (const float*)d_in[9];
    const float* b2     = (const float*)d_in[10];
    const float* p1_sw  = (const float*)d_in[11];
    const float* p1_tw  = (const float*)d_in[13];
    const float* p1_tb  = (const float*)d_in[14];
    const float* p2_sw  = (const float*)d_in[15];
    const float* p2_tw  = (const float*)d_in[17];
    const float* p2_tb  = (const float*)d_in[18];
    const float* c1w    = (const float*)d_in[19];
    const float* c1b    = (const float*)d_in[20];
    const float* c2w    = (const float*)d_in[21];
    const float* c2b    = (const float*)d_in[22];
    float* out = (float*)d_out;

    float*    hlin  = sym(g_hlin);
    float*    hout  = sym(g_hout);
    float*    es    = sym(g_es);
    float*    ed    = sym(g_ed);
    int*      off   = (int*)sym(g_off);
    int*      csrc  = (int*)sym(g_csrc);
    float*    selb  = sym(g_sel);
    float*    pool1 = sym(g_pool1);
    float*    pool2 = sym(g_pool2);

    dim3 t256(256);

    // ---- CSR build ----
    csr_build<<<BB, t256>>>(ei);

    // ---- GAT layer 1 ----
    tf32_gemm<<<dim3(CC / 128, NN / 128), t256>>>(x, W1, nullptr, hlin, NN, CC, FIN);
    esed_kernel<<<(NN * HH) / 8, t256>>>(hlin, asrc1, adst1, es, ed);
    gat_fused<<<(NN * 32) / 256, t256>>>(off, csrc, es, ed, hlin, b1, hout);

    // ---- GAT layer 2 ----
    tf32_gemm<<<dim3(CC / 128, NN / 128), t256>>>(hout, W2, nullptr, hlin, NN, CC, CC);
    esed_kernel<<<(NN * HH) / 8, t256>>>(hlin, asrc2, adst2, es, ed);
    gat_fused<<<(NN * 32) / 256, t256>>>(off, csrc, es, ed, hlin, b2, hout);

    // ---- Pool 1 (top-256 of 512 per graph) ----
    pool_fused<NPG, K1><<<BB, NPG>>>(hout, p1_sw, selb);
    tf32_gemm<<<dim3(CC / 128, (BB * K1) / 128), t256>>>(selb, p1_tw, p1_tb, pool1,
                                                         BB * K1, CC, CC);

    // ---- Pool 2 (top-128 of 256 per graph) ----
    pool_fused<K1, K2><<<BB, K1>>>(pool1, p2_sw, selb);
    tf32_gemm<<<dim3(CC / 128, (BB * K2) / 128), t256>>>(selb, p2_tw, p2_tb, pool2,
                                                         BB * K2, CC, CC);

    // ---- readout ----
    readout_fused<<<BB, t256>>>(pool2, c1w, c1b, c2w, c2b, out);
}